// round 2
// baseline (speedup 1.0000x reference)
#include <cuda_runtime.h>

// NonLocalBlock: B=8, H=W=64 (N=4096), C=256, Cb=128, pooled keys M=2048.
// out = x + softmax(theta @ phiP^T) @ gP @ W_out
//   theta = xf @ W_theta            [B,N,128]
//   phiP  = maxpool2(xf @ W_phi)    [B,M,128]
//   gP    = maxpool2(xf @ W_g)      [B,M,128]

#define NB 8
#define NN 4096
#define NM 2048
#define NC 256
#define ND 128

// Scratch (allocation-free rule: __device__ globals). ~80 MB total.
__device__ float g_theta[NB * NN * ND];
__device__ float g_phi  [NB * NN * ND];
__device__ float g_gg   [NB * NN * ND];
__device__ float g_phiP [NB * NM * ND];
__device__ float g_gP   [NB * NM * ND];
__device__ float g_y    [NB * NN * ND];

// ---------------------------------------------------------------------------
// Projection GEMM: [32768,256] @ [256,128] for 3 weights (blockIdx.z selects).
// Tile 64 rows x 128 cols, K-step 32. 256 threads, each 4x8 micro-tile.
// ---------------------------------------------------------------------------
__global__ __launch_bounds__(256) void proj_kernel(
    const float* __restrict__ x,
    const float* __restrict__ Wt,
    const float* __restrict__ Wp,
    const float* __restrict__ Wg)
{
    __shared__ float As[32][65];   // transposed A tile, padded (conflict-free)
    __shared__ float Ws[32][ND];

    const float* W;
    float* out;
    if (blockIdx.z == 0)      { W = Wt; out = g_theta; }
    else if (blockIdx.z == 1) { W = Wp; out = g_phi; }
    else                      { W = Wg; out = g_gg; }

    int tid  = threadIdx.x;
    int row0 = blockIdx.x * 64;
    int rg   = tid & 15;    // rows: rg + 16*i
    int cg   = tid >> 4;    // cols: cg*8 .. +7

    float acc[4][8];
#pragma unroll
    for (int i = 0; i < 4; i++)
#pragma unroll
        for (int j = 0; j < 8; j++) acc[i][j] = 0.f;

    for (int k0 = 0; k0 < NC; k0 += 32) {
        // A tile: 64 rows x 32 k  (512 float4), store transposed As[k][m]
#pragma unroll
        for (int q = 0; q < 2; q++) {
            int li = q * 256 + tid;
            int m  = li >> 3;
            int kk = (li & 7) * 4;
            float4 v = *(const float4*)(x + (row0 + m) * NC + k0 + kk);
            As[kk + 0][m] = v.x; As[kk + 1][m] = v.y;
            As[kk + 2][m] = v.z; As[kk + 3][m] = v.w;
        }
        // W tile: 32 x 128 (1024 float4 / 4 = 256 each? -> 4 float4/thread)
#pragma unroll
        for (int q = 0; q < 4; q++) {
            int li = q * 256 + tid;
            int kk = li >> 5;
            int c4 = (li & 31) * 4;
            *(float4*)&Ws[kk][c4] = *(const float4*)(W + (k0 + kk) * ND + c4);
        }
        __syncthreads();
#pragma unroll
        for (int k = 0; k < 32; k++) {
            float a[4];
#pragma unroll
            for (int i = 0; i < 4; i++) a[i] = As[k][rg + 16 * i];
            float4 w0 = *(float4*)&Ws[k][cg * 8];
            float4 w1 = *(float4*)&Ws[k][cg * 8 + 4];
#pragma unroll
            for (int i = 0; i < 4; i++) {
                acc[i][0] += a[i] * w0.x; acc[i][1] += a[i] * w0.y;
                acc[i][2] += a[i] * w0.z; acc[i][3] += a[i] * w0.w;
                acc[i][4] += a[i] * w1.x; acc[i][5] += a[i] * w1.y;
                acc[i][6] += a[i] * w1.z; acc[i][7] += a[i] * w1.w;
            }
        }
        __syncthreads();
    }
#pragma unroll
    for (int i = 0; i < 4; i++) {
        int r = row0 + rg + 16 * i;
        float4 v0 = make_float4(acc[i][0], acc[i][1], acc[i][2], acc[i][3]);
        float4 v1 = make_float4(acc[i][4], acc[i][5], acc[i][6], acc[i][7]);
        *(float4*)(out + r * ND + cg * 8)     = v0;
        *(float4*)(out + r * ND + cg * 8 + 4) = v1;
    }
}

// ---------------------------------------------------------------------------
// MaxPool1D(2) along spatial axis for phi and g.
// ---------------------------------------------------------------------------
__global__ __launch_bounds__(256) void pool_kernel()
{
    int idx4   = blockIdx.x * 256 + threadIdx.x;   // float4 index
    int total4 = NB * NM * ND / 4;
    if (idx4 >= total4) return;
    int d4 = idx4 % (ND / 4);
    int r  = (idx4 / (ND / 4)) % NM;
    int b  = idx4 / ((ND / 4) * NM);
    int src = ((b * NN + 2 * r) * ND) / 4 + d4;    // float4 units

    const float4* p = (const float4*)g_phi;
    const float4* g = (const float4*)g_gg;
    float4 a = p[src], a2 = p[src + ND / 4];
    float4 c = g[src], c2 = g[src + ND / 4];
    ((float4*)g_phiP)[idx4] = make_float4(fmaxf(a.x, a2.x), fmaxf(a.y, a2.y),
                                          fmaxf(a.z, a2.z), fmaxf(a.w, a2.w));
    ((float4*)g_gP)[idx4]   = make_float4(fmaxf(c.x, c2.x), fmaxf(c.y, c2.y),
                                          fmaxf(c.z, c2.z), fmaxf(c.w, c2.w));
}

// ---------------------------------------------------------------------------
// Flash-style attention: per (batch, 64-row Q tile). Online softmax over
// M=2048 keys in 64-key chunks. K and G share one smem buffer (loaded in
// two phases per chunk). Y accumulator (64x128) lives in registers.
// ---------------------------------------------------------------------------
__global__ __launch_bounds__(256, 2) void attn_kernel()
{
    extern __shared__ float sm[];
    float (*Qs)[132] = (float(*)[132])sm;                 // 64x132
    float (*KG)[132] = (float(*)[132])(sm + 64 * 132);    // 64x132 (K then G)
    float (*Ss)[65]  = (float(*)[65]) (sm + 2 * 64 * 132);// 64x65 scores/probs
    float* rowm      = sm + 2 * 64 * 132 + 64 * 65;
    float* rowl      = rowm + 64;
    float* rowscale  = rowl + 64;

    int tid = threadIdx.x;
    int b   = blockIdx.y;
    int q0  = blockIdx.x * 64;
    const float* th = g_theta + (b * NN + q0) * ND;
    const float* ph = g_phiP + b * NM * ND;
    const float* gp = g_gP   + b * NM * ND;

    // Load Q tile (64x128)
#pragma unroll
    for (int q = 0; q < 8; q++) {
        int li = q * 256 + tid;
        int r  = li >> 5;
        int c4 = (li & 31) * 4;
        *(float4*)&Qs[r][c4] = *(const float4*)(th + r * ND + c4);
    }
    if (tid < 64) { rowm[tid] = -1e30f; rowl[tid] = 0.f; }

    float yacc[32];
#pragma unroll
    for (int c = 0; c < 32; c++) yacc[c] = 0.f;
    int ry = tid & 63;           // Y row
    int c0 = (tid >> 6) * 32;    // Y col block
    int rg = tid & 15;           // score rows: rg + 16*i
    int jg = tid >> 4;           // score cols: jg + 16*j

    for (int kc = 0; kc < NM; kc += 64) {
        __syncthreads();   // protect KG/Ss from previous-iteration readers
        // Load K chunk
#pragma unroll
        for (int q = 0; q < 8; q++) {
            int li = q * 256 + tid;
            int r  = li >> 5;
            int c4 = (li & 31) * 4;
            *(float4*)&KG[r][c4] = *(const float4*)(ph + (kc + r) * ND + c4);
        }
        __syncthreads();
        // Scores: 16 (r,j) pairs/thread, k vectorized by 4
        float sacc[4][4];
#pragma unroll
        for (int i = 0; i < 4; i++)
#pragma unroll
            for (int j = 0; j < 4; j++) sacc[i][j] = 0.f;
#pragma unroll
        for (int k = 0; k < ND; k += 4) {
            float4 qv[4], kv[4];
#pragma unroll
            for (int i = 0; i < 4; i++) qv[i] = *(float4*)&Qs[rg + 16 * i][k];
#pragma unroll
            for (int j = 0; j < 4; j++) kv[j] = *(float4*)&KG[jg + 16 * j][k];
#pragma unroll
            for (int i = 0; i < 4; i++)
#pragma unroll
                for (int j = 0; j < 4; j++)
                    sacc[i][j] += qv[i].x * kv[j].x + qv[i].y * kv[j].y
                                + qv[i].z * kv[j].z + qv[i].w * kv[j].w;
        }
#pragma unroll
        for (int i = 0; i < 4; i++)
#pragma unroll
            for (int j = 0; j < 4; j++)
                Ss[rg + 16 * i][jg + 16 * j] = sacc[i][j];
        __syncthreads();
        // Reload buffer with G chunk (K reads all done)
#pragma unroll
        for (int q = 0; q < 8; q++) {
            int li = q * 256 + tid;
            int r  = li >> 5;
            int c4 = (li & 31) * 4;
            *(float4*)&KG[r][c4] = *(const float4*)(gp + (kc + r) * ND + c4);
        }
        // Online softmax (one thread per row)
        if (tid < 64) {
            int r = tid;
            float cm = -1e30f;
#pragma unroll 8
            for (int j = 0; j < 64; j++) cm = fmaxf(cm, Ss[r][j]);
            float nm = fmaxf(rowm[r], cm);
            float sc = __expf(rowm[r] - nm);
            float s  = 0.f;
#pragma unroll 8
            for (int j = 0; j < 64; j++) {
                float pv = __expf(Ss[r][j] - nm);
                Ss[r][j] = pv;
                s += pv;
            }
            rowl[r]     = rowl[r] * sc + s;
            rowm[r]     = nm;
            rowscale[r] = sc;
        }
        __syncthreads();
        // Y update: rescale + accumulate P @ G
        float sc = rowscale[ry];
#pragma unroll
        for (int c = 0; c < 32; c++) yacc[c] *= sc;
#pragma unroll 4
        for (int j = 0; j < 64; j++) {
            float pv = Ss[ry][j];
#pragma unroll
            for (int c4 = 0; c4 < 32; c4 += 4) {
                float4 gv = *(float4*)&KG[j][c0 + c4];
                yacc[c4 + 0] += pv * gv.x; yacc[c4 + 1] += pv * gv.y;
                yacc[c4 + 2] += pv * gv.z; yacc[c4 + 3] += pv * gv.w;
            }
        }
    }
    // Normalize and write y
    float inv = 1.f / rowl[ry];
    float* yo = g_y + (b * NN + q0 + ry) * ND + c0;
#pragma unroll
    for (int c4 = 0; c4 < 32; c4 += 4) {
        float4 v = make_float4(yacc[c4] * inv, yacc[c4 + 1] * inv,
                               yacc[c4 + 2] * inv, yacc[c4 + 3] * inv);
        *(float4*)(yo + c4) = v;
    }
}

// ---------------------------------------------------------------------------
// Output GEMM + residual: out = x + y @ W_out.  [32768,128] @ [128,256].
// ---------------------------------------------------------------------------
__global__ __launch_bounds__(256) void out_kernel(
    const float* __restrict__ x,
    const float* __restrict__ Wout,
    float* __restrict__ out)
{
    __shared__ float As[32][65];
    __shared__ float Ws[32][128];

    int tid  = threadIdx.x;
    int row0 = blockIdx.x * 64;
    int col0 = blockIdx.y * 128;
    int rg   = tid & 15;
    int cg   = tid >> 4;

    float acc[4][8];
#pragma unroll
    for (int i = 0; i < 4; i++)
#pragma unroll
        for (int j = 0; j < 8; j++) acc[i][j] = 0.f;

    for (int k0 = 0; k0 < ND; k0 += 32) {
#pragma unroll
        for (int q = 0; q < 2; q++) {
            int li = q * 256 + tid;
            int m  = li >> 3;
            int kk = (li & 7) * 4;
            float4 v = *(const float4*)(g_y + (row0 + m) * ND + k0 + kk);
            As[kk + 0][m] = v.x; As[kk + 1][m] = v.y;
            As[kk + 2][m] = v.z; As[kk + 3][m] = v.w;
        }
#pragma unroll
        for (int q = 0; q < 4; q++) {
            int li = q * 256 + tid;
            int kk = li >> 5;
            int c4 = (li & 31) * 4;
            *(float4*)&Ws[kk][c4] = *(const float4*)(Wout + (k0 + kk) * NC + col0 + c4);
        }
        __syncthreads();
#pragma unroll
        for (int k = 0; k < 32; k++) {
            float a[4];
#pragma unroll
            for (int i = 0; i < 4; i++) a[i] = As[k][rg + 16 * i];
            float4 w0 = *(float4*)&Ws[k][cg * 8];
            float4 w1 = *(float4*)&Ws[k][cg * 8 + 4];
#pragma unroll
            for (int i = 0; i < 4; i++) {
                acc[i][0] += a[i] * w0.x; acc[i][1] += a[i] * w0.y;
                acc[i][2] += a[i] * w0.z; acc[i][3] += a[i] * w0.w;
                acc[i][4] += a[i] * w1.x; acc[i][5] += a[i] * w1.y;
                acc[i][6] += a[i] * w1.z; acc[i][7] += a[i] * w1.w;
            }
        }
        __syncthreads();
    }
#pragma unroll
    for (int i = 0; i < 4; i++) {
        int r = row0 + rg + 16 * i;
        const float* xr = x + r * NC + col0 + cg * 8;
        float* orow     = out + r * NC + col0 + cg * 8;
        float4 x0 = *(const float4*)xr;
        float4 x1 = *(const float4*)(xr + 4);
        float4 v0 = make_float4(acc[i][0] + x0.x, acc[i][1] + x0.y,
                                acc[i][2] + x0.z, acc[i][3] + x0.w);
        float4 v1 = make_float4(acc[i][4] + x1.x, acc[i][5] + x1.y,
                                acc[i][6] + x1.z, acc[i][7] + x1.w);
        *(float4*)orow       = v0;
        *(float4*)(orow + 4) = v1;
    }
}

// ---------------------------------------------------------------------------
extern "C" void kernel_launch(void* const* d_in, const int* in_sizes, int n_in,
                              void* d_out, int out_size)
{
    const float* x  = (const float*)d_in[0];
    const float* Wt = (const float*)d_in[1];
    const float* Wp = (const float*)d_in[2];
    const float* Wg = (const float*)d_in[3];
    const float* Wo = (const float*)d_in[4];
    float* out      = (float*)d_out;

    const int ATTN_SMEM = (2 * 64 * 132 + 64 * 65 + 192) * 4;  // 84992 B
    cudaFuncSetAttribute(attn_kernel,
                         cudaFuncAttributeMaxDynamicSharedMemorySize, ATTN_SMEM);

    proj_kernel<<<dim3(512, 1, 3), 256>>>(x, Wt, Wp, Wg);
    pool_kernel<<<(NB * NM * ND / 4 + 255) / 256, 256>>>();
    attn_kernel<<<dim3(NN / 64, NB), 256, ATTN_SMEM>>>();
    out_kernel<<<dim3(512, 2), 256>>>(x, Wo, out);
}

// round 5
// speedup vs baseline: 1.9345x; 1.9345x over previous
#include <cuda_runtime.h>
#include <cstdint>

// NonLocalBlock B=8, N=4096, M=2048, C=256, d=128
#define NB 8
#define NN 4096
#define NM 2048
#define NC 256
#define ND 128

// __device__ scratch (allocation-free rule). ~336 MB total.
__device__ float g_theta[NB * NN * ND];
__device__ float g_phi  [NB * NN * ND];
__device__ float g_gg   [NB * NN * ND];
__device__ float g_phiP [NB * NM * ND];          // [b][m][d]
__device__ float g_gPt  [NB * ND * NM];          // [b][d][m] (transposed for PV B-operand)
__device__ float g_S    [NB * NN * NM];          // scores -> probabilities in place (256 MB)
__device__ float g_y    [NB * NN * ND];

// ---------------------------------------------------------------------------
// TF32 helpers (warp-level mma.sync — supported on plain sm_103 target)
// ---------------------------------------------------------------------------
__device__ __forceinline__ uint32_t f2tf32(float v) {
    uint32_t r;
    asm("cvt.rna.tf32.f32 %0, %1;" : "=r"(r) : "f"(v));
    return r;
}

__device__ __forceinline__ void mma_tf32(float (&d)[4],
                                         uint32_t a0, uint32_t a1, uint32_t a2, uint32_t a3,
                                         uint32_t b0, uint32_t b1) {
    asm volatile(
        "mma.sync.aligned.m16n8k8.row.col.f32.tf32.tf32.f32 "
        "{%0,%1,%2,%3}, {%4,%5,%6,%7}, {%8,%9}, {%0,%1,%2,%3};"
        : "+f"(d[0]), "+f"(d[1]), "+f"(d[2]), "+f"(d[3])
        : "r"(a0), "r"(a1), "r"(a2), "r"(a3), "r"(b0), "r"(b1));
}

// ---------------------------------------------------------------------------
// Projection GEMM (fp32 SIMT): [32768,256]@[256,128] for 3 weights
// ---------------------------------------------------------------------------
__global__ __launch_bounds__(256) void proj_kernel(
    const float* __restrict__ x, const float* __restrict__ Wt,
    const float* __restrict__ Wp, const float* __restrict__ Wg)
{
    __shared__ float As[32][65];
    __shared__ float Ws[32][ND];
    const float* W; float* out;
    if (blockIdx.z == 0)      { W = Wt; out = g_theta; }
    else if (blockIdx.z == 1) { W = Wp; out = g_phi; }
    else                      { W = Wg; out = g_gg; }
    int tid = threadIdx.x, row0 = blockIdx.x * 64;
    int rg = tid & 15, cg = tid >> 4;
    float acc[4][8];
#pragma unroll
    for (int i = 0; i < 4; i++)
#pragma unroll
        for (int j = 0; j < 8; j++) acc[i][j] = 0.f;
    for (int k0 = 0; k0 < NC; k0 += 32) {
#pragma unroll
        for (int q = 0; q < 2; q++) {
            int li = q * 256 + tid, m = li >> 3, kk = (li & 7) * 4;
            float4 v = *(const float4*)(x + (row0 + m) * NC + k0 + kk);
            As[kk][m] = v.x; As[kk + 1][m] = v.y; As[kk + 2][m] = v.z; As[kk + 3][m] = v.w;
        }
#pragma unroll
        for (int q = 0; q < 4; q++) {
            int li = q * 256 + tid, kk = li >> 5, c4 = (li & 31) * 4;
            *(float4*)&Ws[kk][c4] = *(const float4*)(W + (k0 + kk) * ND + c4);
        }
        __syncthreads();
#pragma unroll
        for (int k = 0; k < 32; k++) {
            float a[4];
#pragma unroll
            for (int i = 0; i < 4; i++) a[i] = As[k][rg + 16 * i];
            float4 w0 = *(float4*)&Ws[k][cg * 8];
            float4 w1 = *(float4*)&Ws[k][cg * 8 + 4];
#pragma unroll
            for (int i = 0; i < 4; i++) {
                acc[i][0] += a[i] * w0.x; acc[i][1] += a[i] * w0.y;
                acc[i][2] += a[i] * w0.z; acc[i][3] += a[i] * w0.w;
                acc[i][4] += a[i] * w1.x; acc[i][5] += a[i] * w1.y;
                acc[i][6] += a[i] * w1.z; acc[i][7] += a[i] * w1.w;
            }
        }
        __syncthreads();
    }
#pragma unroll
    for (int i = 0; i < 4; i++) {
        int r = row0 + rg + 16 * i;
        *(float4*)(out + r * ND + cg * 8)     = make_float4(acc[i][0], acc[i][1], acc[i][2], acc[i][3]);
        *(float4*)(out + r * ND + cg * 8 + 4) = make_float4(acc[i][4], acc[i][5], acc[i][6], acc[i][7]);
    }
}

// ---------------------------------------------------------------------------
// MaxPool(2): phi -> phiP (row-major), g -> gPt (transposed [b][d][m])
// ---------------------------------------------------------------------------
__global__ __launch_bounds__(256) void pool_kernel()
{
    int idx4 = blockIdx.x * 256 + threadIdx.x;
    int total4 = NB * NM * ND / 4;
    if (idx4 >= total4) return;
    int d4 = idx4 % (ND / 4);
    int r  = (idx4 / (ND / 4)) % NM;
    int b  = idx4 / ((ND / 4) * NM);
    int src = ((b * NN + 2 * r) * ND) / 4 + d4;
    const float4* p = (const float4*)g_phi;
    const float4* g = (const float4*)g_gg;
    float4 a = p[src], a2 = p[src + ND / 4];
    float4 c = g[src], c2 = g[src + ND / 4];
    ((float4*)g_phiP)[idx4] = make_float4(fmaxf(a.x, a2.x), fmaxf(a.y, a2.y),
                                          fmaxf(a.z, a2.z), fmaxf(a.w, a2.w));
    int d0 = d4 * 4;
    g_gPt[(b * ND + d0 + 0) * NM + r] = fmaxf(c.x, c2.x);
    g_gPt[(b * ND + d0 + 1) * NM + r] = fmaxf(c.y, c2.y);
    g_gPt[(b * ND + d0 + 2) * NM + r] = fmaxf(c.z, c2.z);
    g_gPt[(b * ND + d0 + 3) * NM + r] = fmaxf(c.w, c2.w);
}

// ---------------------------------------------------------------------------
// Shared tiling constants: 128 rows x 64-col K-chunk per stage, stride 68.
// Max smem element read: 127*68 + 59 + 4 = 8699 < 8704 (in bounds).
// ---------------------------------------------------------------------------
#define TSTR 68

// ---------------------------------------------------------------------------
// GEMM1 (HMMA 3xTF32): S[128 x 128] = theta @ phiP^T, K=128 in 2 chunks of 64
// grid (32 qtiles, 16 mtiles, 8 b), 256 threads = 8 warps (4x2),
// each warp computes 32 rows x 64 cols.
// ---------------------------------------------------------------------------
__global__ __launch_bounds__(256, 2) void qk_kernel()
{
    extern __shared__ float sm[];
    float* Qs = sm;                   // 128 x TSTR (64 cols used)
    float* Ks = sm + 128 * TSTR;      // 128 x TSTR

    int tid = threadIdx.x;
    int b = blockIdx.z, q0 = blockIdx.x * 128, m0 = blockIdx.y * 128;
    const float* Ap = g_theta + (size_t)(b * NN + q0) * ND;
    const float* Bp = g_phiP + (size_t)(b * NM + m0) * ND;

    int lane = tid & 31, g = lane >> 2, t = lane & 3;
    int wid = tid >> 5, wr = wid >> 1, wc = wid & 1;
    int r0 = wr * 32, c0 = wc * 64;

    float acc[2][8][4];
#pragma unroll
    for (int mt = 0; mt < 2; mt++)
#pragma unroll
        for (int nt = 0; nt < 8; nt++)
#pragma unroll
            for (int i = 0; i < 4; i++) acc[mt][nt][i] = 0.f;

#pragma unroll 1
    for (int kc = 0; kc < 2; kc++) {
        int k0 = kc * 64;
        // Stage 128 rows x 64 cols of Q and K (8 iters x 256 thr x float4)
#pragma unroll
        for (int q = 0; q < 8; q++) {
            int li = q * 256 + tid, r = li >> 4, c = (li & 15) * 4;
            *(float4*)&Qs[r * TSTR + c] = *(const float4*)(Ap + r * ND + k0 + c);
            *(float4*)&Ks[r * TSTR + c] = *(const float4*)(Bp + r * ND + k0 + c);
        }
        __syncthreads();
#pragma unroll 2
        for (int kst = 0; kst < 8; kst++) {
            int kk = kst * 8;
            uint32_t ah[2][4], al[2][4];
#pragma unroll
            for (int mt = 0; mt < 2; mt++) {
                const float* ab = Qs + (r0 + 16 * mt + g) * TSTR + kk + t;
                float v0 = ab[0], v1 = ab[8 * TSTR], v2 = ab[4], v3 = ab[8 * TSTR + 4];
                ah[mt][0] = f2tf32(v0); al[mt][0] = f2tf32(v0 - __uint_as_float(ah[mt][0]));
                ah[mt][1] = f2tf32(v1); al[mt][1] = f2tf32(v1 - __uint_as_float(ah[mt][1]));
                ah[mt][2] = f2tf32(v2); al[mt][2] = f2tf32(v2 - __uint_as_float(ah[mt][2]));
                ah[mt][3] = f2tf32(v3); al[mt][3] = f2tf32(v3 - __uint_as_float(ah[mt][3]));
            }
#pragma unroll
            for (int nt = 0; nt < 8; nt++) {
                const float* kb = Ks + (c0 + 8 * nt + g) * TSTR + kk + t;
                float w0 = kb[0], w1 = kb[4];
                uint32_t bh0 = f2tf32(w0), bh1 = f2tf32(w1);
                uint32_t bl0 = f2tf32(w0 - __uint_as_float(bh0));
                uint32_t bl1 = f2tf32(w1 - __uint_as_float(bh1));
#pragma unroll
                for (int mt = 0; mt < 2; mt++) {
                    mma_tf32(acc[mt][nt], ah[mt][0], ah[mt][1], ah[mt][2], ah[mt][3], bh0, bh1);
                    mma_tf32(acc[mt][nt], ah[mt][0], ah[mt][1], ah[mt][2], ah[mt][3], bl0, bl1);
                    mma_tf32(acc[mt][nt], al[mt][0], al[mt][1], al[mt][2], al[mt][3], bh0, bh1);
                }
            }
        }
        __syncthreads();
    }

#pragma unroll
    for (int mt = 0; mt < 2; mt++) {
        float* So0 = g_S + (size_t)(b * NN + q0 + r0 + 16 * mt + g) * NM + m0 + c0;
        float* So1 = So0 + 8 * (size_t)NM;
#pragma unroll
        for (int nt = 0; nt < 8; nt++) {
            *(float2*)(So0 + 8 * nt + 2 * t) = make_float2(acc[mt][nt][0], acc[mt][nt][1]);
            *(float2*)(So1 + 8 * nt + 2 * t) = make_float2(acc[mt][nt][2], acc[mt][nt][3]);
        }
    }
}

// ---------------------------------------------------------------------------
// Softmax: one warp per row of 2048, in-place normalize to probabilities.
// ---------------------------------------------------------------------------
__global__ __launch_bounds__(256) void softmax_kernel()
{
    int wid = threadIdx.x >> 5, lane = threadIdx.x & 31;
    int row = blockIdx.x * 8 + wid;
    float* Sp = g_S + (size_t)row * NM;
    float4 v[16];
#pragma unroll
    for (int j = 0; j < 16; j++) v[j] = *(float4*)(Sp + (j * 32 + lane) * 4);
    float m = -1e30f;
#pragma unroll
    for (int j = 0; j < 16; j++)
        m = fmaxf(m, fmaxf(fmaxf(v[j].x, v[j].y), fmaxf(v[j].z, v[j].w)));
#pragma unroll
    for (int o = 16; o > 0; o >>= 1) m = fmaxf(m, __shfl_xor_sync(0xFFFFFFFF, m, o));
    float s = 0.f;
#pragma unroll
    for (int j = 0; j < 16; j++) {
        v[j].x = __expf(v[j].x - m); v[j].y = __expf(v[j].y - m);
        v[j].z = __expf(v[j].z - m); v[j].w = __expf(v[j].w - m);
        s += v[j].x + v[j].y + v[j].z + v[j].w;
    }
#pragma unroll
    for (int o = 16; o > 0; o >>= 1) s += __shfl_xor_sync(0xFFFFFFFF, s, o);
    float inv = 1.f / s;
#pragma unroll
    for (int j = 0; j < 16; j++) {
        v[j].x *= inv; v[j].y *= inv; v[j].z *= inv; v[j].w *= inv;
        *(float4*)(Sp + (j * 32 + lane) * 4) = v[j];
    }
}

// ---------------------------------------------------------------------------
// GEMM2 (HMMA 1xTF32): Y[128 x 128] = P[128 x 2048] @ G[2048 x 128], K=2048
// grid (32 qtiles, 8 b), 256 threads, warps 4x2: each 32 rows x 64 d-cols.
// ---------------------------------------------------------------------------
__global__ __launch_bounds__(256, 2) void pv_kernel()
{
    extern __shared__ float sm[];
    float* Ps = sm;                   // 128 q x TSTR (64 used)
    float* Gs = sm + 128 * TSTR;      // 128 d x TSTR (64 used)

    int tid = threadIdx.x;
    int b = blockIdx.y, q0 = blockIdx.x * 128;
    const float* Ap = g_S + (size_t)(b * NN + q0) * NM;
    const float* Bp = g_gPt + (size_t)b * ND * NM;

    int lane = tid & 31, g = lane >> 2, t = lane & 3;
    int wid = tid >> 5, wr = wid >> 1, wc = wid & 1;
    int r0 = wr * 32, c0 = wc * 64;

    float acc[2][8][4];
#pragma unroll
    for (int mt = 0; mt < 2; mt++)
#pragma unroll
        for (int nt = 0; nt < 8; nt++)
#pragma unroll
            for (int i = 0; i < 4; i++) acc[mt][nt][i] = 0.f;

#pragma unroll 1
    for (int kc = 0; kc < 32; kc++) {
        int k0 = kc * 64;
#pragma unroll
        for (int q = 0; q < 8; q++) {
            int li = q * 256 + tid, r = li >> 4, c = (li & 15) * 4;
            *(float4*)&Ps[r * TSTR + c] = *(const float4*)(Ap + (size_t)r * NM + k0 + c);
            *(float4*)&Gs[r * TSTR + c] = *(const float4*)(Bp + (size_t)r * NM + k0 + c);
        }
        __syncthreads();
#pragma unroll 2
        for (int kst = 0; kst < 8; kst++) {
            int kk = kst * 8;
            uint32_t a[2][4];
#pragma unroll
            for (int mt = 0; mt < 2; mt++) {
                const float* ab = Ps + (r0 + 16 * mt + g) * TSTR + kk + t;
                a[mt][0] = f2tf32(ab[0]);
                a[mt][1] = f2tf32(ab[8 * TSTR]);
                a[mt][2] = f2tf32(ab[4]);
                a[mt][3] = f2tf32(ab[8 * TSTR + 4]);
            }
#pragma unroll
            for (int nt = 0; nt < 8; nt++) {
                const float* gb = Gs + (c0 + 8 * nt + g) * TSTR + kk + t;
                uint32_t b0 = f2tf32(gb[0]), b1 = f2tf32(gb[4]);
#pragma unroll
                for (int mt = 0; mt < 2; mt++)
                    mma_tf32(acc[mt][nt], a[mt][0], a[mt][1], a[mt][2], a[mt][3], b0, b1);
            }
        }
        __syncthreads();
    }

#pragma unroll
    for (int mt = 0; mt < 2; mt++) {
        float* Yo0 = g_y + (size_t)(b * NN + q0 + r0 + 16 * mt + g) * ND + c0;
        float* Yo1 = Yo0 + 8 * (size_t)ND;
#pragma unroll
        for (int nt = 0; nt < 8; nt++) {
            *(float2*)(Yo0 + 8 * nt + 2 * t) = make_float2(acc[mt][nt][0], acc[mt][nt][1]);
            *(float2*)(Yo1 + 8 * nt + 2 * t) = make_float2(acc[mt][nt][2], acc[mt][nt][3]);
        }
    }
}

// ---------------------------------------------------------------------------
// Output GEMM + residual (fp32 SIMT)
// ---------------------------------------------------------------------------
__global__ __launch_bounds__(256) void out_kernel(
    const float* __restrict__ x, const float* __restrict__ Wout, float* __restrict__ out)
{
    __shared__ float As[32][65];
    __shared__ float Ws[32][128];
    int tid = threadIdx.x, row0 = blockIdx.x * 64, col0 = blockIdx.y * 128;
    int rg = tid & 15, cg = tid >> 4;
    float acc[4][8];
#pragma unroll
    for (int i = 0; i < 4; i++)
#pragma unroll
        for (int j = 0; j < 8; j++) acc[i][j] = 0.f;
    for (int k0 = 0; k0 < ND; k0 += 32) {
#pragma unroll
        for (int q = 0; q < 2; q++) {
            int li = q * 256 + tid, m = li >> 3, kk = (li & 7) * 4;
            float4 v = *(const float4*)(g_y + (row0 + m) * ND + k0 + kk);
            As[kk][m] = v.x; As[kk + 1][m] = v.y; As[kk + 2][m] = v.z; As[kk + 3][m] = v.w;
        }
#pragma unroll
        for (int q = 0; q < 4; q++) {
            int li = q * 256 + tid, kk = li >> 5, c4 = (li & 31) * 4;
            *(float4*)&Ws[kk][c4] = *(const float4*)(Wout + (k0 + kk) * NC + col0 + c4);
        }
        __syncthreads();
#pragma unroll
        for (int k = 0; k < 32; k++) {
            float a[4];
#pragma unroll
            for (int i = 0; i < 4; i++) a[i] = As[k][rg + 16 * i];
            float4 w0 = *(float4*)&Ws[k][cg * 8];
            float4 w1 = *(float4*)&Ws[k][cg * 8 + 4];
#pragma unroll
            for (int i = 0; i < 4; i++) {
                acc[i][0] += a[i] * w0.x; acc[i][1] += a[i] * w0.y;
                acc[i][2] += a[i] * w0.z; acc[i][3] += a[i] * w0.w;
                acc[i][4] += a[i] * w1.x; acc[i][5] += a[i] * w1.y;
                acc[i][6] += a[i] * w1.z; acc[i][7] += a[i] * w1.w;
            }
        }
        __syncthreads();
    }
#pragma unroll
    for (int i = 0; i < 4; i++) {
        int r = row0 + rg + 16 * i;
        const float* xr = x + r * NC + col0 + cg * 8;
        float* orow = out + r * NC + col0 + cg * 8;
        float4 x0 = *(const float4*)xr, x1 = *(const float4*)(xr + 4);
        *(float4*)orow = make_float4(acc[i][0] + x0.x, acc[i][1] + x0.y,
                                     acc[i][2] + x0.z, acc[i][3] + x0.w);
        *(float4*)(orow + 4) = make_float4(acc[i][4] + x1.x, acc[i][5] + x1.y,
                                           acc[i][6] + x1.z, acc[i][7] + x1.w);
    }
}

// ---------------------------------------------------------------------------
extern "C" void kernel_launch(void* const* d_in, const int* in_sizes, int n_in,
                              void* d_out, int out_size)
{
    const float* x  = (const float*)d_in[0];
    const float* Wt = (const float*)d_in[1];
    const float* Wp = (const float*)d_in[2];
    const float* Wg = (const float*)d_in[3];
    const float* Wo = (const float*)d_in[4];
    float* out      = (float*)d_out;

    const int MMA_SMEM = 2 * 128 * TSTR * 4;   // 69632 B
    cudaFuncSetAttribute(qk_kernel, cudaFuncAttributeMaxDynamicSharedMemorySize, MMA_SMEM);
    cudaFuncSetAttribute(pv_kernel, cudaFuncAttributeMaxDynamicSharedMemorySize, MMA_SMEM);

    proj_kernel<<<dim3(512, 1, 3), 256>>>(x, Wt, Wp, Wg);
    pool_kernel<<<(NB * NM * ND / 4 + 255) / 256, 256>>>();
    qk_kernel<<<dim3(32, 16, 8), 256, MMA_SMEM>>>();
    softmax_kernel<<<NB * NN / 8, 256>>>();
    pv_kernel<<<dim3(32, 8), 256, MMA_SMEM>>>();
    out_kernel<<<dim3(512, 2), 256>>>(x, Wo, out);
}